// round 1
// baseline (speedup 1.0000x reference)
#include <cuda_runtime.h>

// Fused Allen-Cahn step:
//   out = ALPHA*x - ALPHA*x^3 + BETA*(N + S + W + E - 4x)
// with replication padding on H and W. Shape: (16, 1, 1024, 1024) fp32.
// HBM-bound: 64MB in + 64MB out.

#define ALPHA 400.0f
#define BETA  10000.0f

static constexpr int W = 1024;
static constexpr int H = 1024;
static constexpr int NIMG = 16;
static constexpr int VEC = 4;           // float4
static constexpr int TPB = W / VEC;     // 256 threads = one row

__device__ __forceinline__ float pt(float x, float n, float s, float w, float e) {
    // x*(ALPHA - 4*BETA) - ALPHA*x^3 + BETA*(n+s+w+e)
    const float c0 = ALPHA - 4.0f * BETA;
    float nb = (n + s) + (w + e);
    return fmaf(BETA, nb, fmaf(c0, x, -ALPHA * x * x * x));
}

__global__ __launch_bounds__(TPB, 8)
void allen_cahn_kernel(const float* __restrict__ in, float* __restrict__ out) {
    const int r   = blockIdx.x;           // row within image
    const int img = blockIdx.y;           // image index
    const int c4  = threadIdx.x;          // float4 column index
    const int base = c4 * VEC;            // element column of .x

    const float* imgp = in + (size_t)img * H * W;
    const int r_up = (r == 0)     ? 0     : r - 1;
    const int r_dn = (r == H - 1) ? H - 1 : r + 1;

    const float4 c  = *reinterpret_cast<const float4*>(imgp + (size_t)r    * W + base);
    const float4 up = *reinterpret_cast<const float4*>(imgp + (size_t)r_up * W + base);
    const float4 dn = *reinterpret_cast<const float4*>(imgp + (size_t)r_dn * W + base);

    // West/east halo scalars with edge clamp (replication pad).
    const float west = (base == 0)         ? c.x : imgp[(size_t)r * W + base - 1];
    const float east = (base + VEC >= W)   ? c.w : imgp[(size_t)r * W + base + VEC];

    float4 o;
    o.x = pt(c.x, up.x, dn.x, west, c.y);
    o.y = pt(c.y, up.y, dn.y, c.x,  c.z);
    o.z = pt(c.z, up.z, dn.z, c.y,  c.w);
    o.w = pt(c.w, up.w, dn.w, c.z,  east);

    *reinterpret_cast<float4*>(out + (size_t)img * H * W + (size_t)r * W + base) = o;
}

extern "C" void kernel_launch(void* const* d_in, const int* in_sizes, int n_in,
                              void* d_out, int out_size) {
    const float* x0 = (const float*)d_in[0];
    float* out = (float*)d_out;
    dim3 grid(H, NIMG);
    allen_cahn_kernel<<<grid, TPB>>>(x0, out);
}